// round 10
// baseline (speedup 1.0000x reference)
#include <cuda_runtime.h>
#include <cuda_bf16.h>
#include <math.h>
#include <stdint.h>

#define B_SZ 1024
#define H_SZ 1024
#define N_SZ 32
#define K_DIM 1024   // = H
#define N2_DIM 2048  // = 2H

// ---------------------------------------------------------------------------
// Scratch (device globals: no allocation allowed)
// ---------------------------------------------------------------------------
__device__ __nv_bfloat16 g_yh[B_SZ * H_SZ];       // hi(gelu(y+uD))
__device__ __nv_bfloat16 g_yl[B_SZ * H_SZ];       // lo residual

// ---------------------------------------------------------------------------
// Kernel 1: complex diag state update + C-readout + GELU skip -> bf16 hi/lo
// 8 threads per (b,h) row, float4 per thread over N=32.
// Streaming loads/stores for the zero-reuse 536MB state stream.
// ---------------------------------------------------------------------------
__global__ __launch_bounds__(256) void s4_update_kernel(
    const float* __restrict__ u,
    const float* __restrict__ sre, const float* __restrict__ sim,
    const float* __restrict__ dAr, const float* __restrict__ dAi,
    const float* __restrict__ dBr, const float* __restrict__ dBi,
    const float* __restrict__ Cr,  const float* __restrict__ Ci,
    const float* __restrict__ D,
    float* __restrict__ ns_re, float* __restrict__ ns_im)
{
    int tid = blockIdx.x * 256 + threadIdx.x;
    int row = tid >> 3;
    int sub = tid & 7;
    int h   = row & (H_SZ - 1);

    long soff = (long)row * N_SZ + sub * 4;
    long poff = (long)h   * N_SZ + sub * 4;

    float4 s_re = __ldcs((const float4*)(sre + soff));
    float4 s_im = __ldcs((const float4*)(sim + soff));
    float4 ar   = *(const float4*)(dAr + poff);
    float4 ai   = *(const float4*)(dAi + poff);
    float4 br   = *(const float4*)(dBr + poff);
    float4 bi   = *(const float4*)(dBi + poff);
    float4 cr   = *(const float4*)(Cr  + poff);
    float4 ci   = *(const float4*)(Ci  + poff);
    float  uv   = u[row];

    float4 nr, ni;
    nr.x = ar.x * s_re.x - ai.x * s_im.x + br.x * uv;
    nr.y = ar.y * s_re.y - ai.y * s_im.y + br.y * uv;
    nr.z = ar.z * s_re.z - ai.z * s_im.z + br.z * uv;
    nr.w = ar.w * s_re.w - ai.w * s_im.w + br.w * uv;
    ni.x = ar.x * s_im.x + ai.x * s_re.x + bi.x * uv;
    ni.y = ar.y * s_im.y + ai.y * s_re.y + bi.y * uv;
    ni.z = ar.z * s_im.z + ai.z * s_re.z + bi.z * uv;
    ni.w = ar.w * s_im.w + ai.w * s_re.w + bi.w * uv;

    __stcs((float4*)(ns_re + soff), nr);
    __stcs((float4*)(ns_im + soff), ni);

    float acc = cr.x * nr.x - ci.x * ni.x
              + cr.y * nr.y - ci.y * ni.y
              + cr.z * nr.z - ci.z * ni.z
              + cr.w * nr.w - ci.w * ni.w;

    acc += __shfl_xor_sync(0xffffffffu, acc, 4);
    acc += __shfl_xor_sync(0xffffffffu, acc, 2);
    acc += __shfl_xor_sync(0xffffffffu, acc, 1);

    if (sub == 0) {
        float y = 2.0f * acc + uv * D[h];
        float g = 0.5f * y * (1.0f + erff(y * 0.70710678118654752f));
        __nv_bfloat16 hi = __float2bfloat16_rn(g);
        g_yh[row] = hi;
        g_yl[row] = __float2bfloat16_rn(g - __bfloat162float(hi));
    }
}

// ---------------------------------------------------------------------------
// Kernel 2 (fused): split-bf16 tensor GEMM + bias + GLU -> y_out
// 512 threads / 16 warps (4M x 4N warp grid, warp tile 32x32).
// CTA: M-tile 128, paired N columns [bn64,+64) and [1024+bn64,+64).
// K-chunk 64, 2-stage cp.async pipeline for A; W fp32 register-prefetch,
// hi/lo split in regs, STS after compute.  3-term split MMA, fp32 accum.
// ---------------------------------------------------------------------------
__device__ __forceinline__ void ldsm_x4(uint32_t& r0, uint32_t& r1,
                                        uint32_t& r2, uint32_t& r3, uint32_t addr)
{
    asm volatile("ldmatrix.sync.aligned.m8n8.x4.shared.b16 {%0,%1,%2,%3}, [%4];\n"
                 : "=r"(r0), "=r"(r1), "=r"(r2), "=r"(r3) : "r"(addr));
}

__device__ __forceinline__ void mma_16816(float* c, const uint32_t* a,
                                          uint32_t b0, uint32_t b1)
{
    asm volatile(
        "mma.sync.aligned.m16n8k16.row.col.f32.bf16.bf16.f32 "
        "{%0,%1,%2,%3}, {%4,%5,%6,%7}, {%8,%9}, {%0,%1,%2,%3};\n"
        : "+f"(c[0]), "+f"(c[1]), "+f"(c[2]), "+f"(c[3])
        : "r"(a[0]), "r"(a[1]), "r"(a[2]), "r"(a[3]), "r"(b0), "r"(b1));
}

__device__ __forceinline__ void cp_async16(uint32_t dst, const void* src)
{
    asm volatile("cp.async.cg.shared.global [%0], [%1], 16;\n"
                 :: "r"(dst), "l"(src));
}

#define GBK   64
#define SM_AH 0
#define SM_AL 16384
#define SM_BH 32768
#define SM_BL 49152
#define STAGE 65536
#define SM_TOTAL (2 * STAGE)
#define ZS_STRIDE 132   // fp32 z staging stride (conflict-breaking)

__global__ __launch_bounds__(512, 1) void gemm_fused_kernel(
    const float* __restrict__ W,
    const float* __restrict__ bias,
    float* __restrict__ y_out)
{
    extern __shared__ char smem[];
    uint32_t sbase = (uint32_t)__cvta_generic_to_shared(smem);

    int tid  = threadIdx.x;
    int lane = tid & 31;
    int wid  = tid >> 5;
    int wm   = (wid & 3) * 32;     // warp M offset: 0/32/64/96
    int wn   = (wid >> 2) * 32;    // warp N offset: 0/32/64/96
    int bm   = blockIdx.y * 128;
    int bn64 = blockIdx.x * 64;    // first-half column base

    float acc[2][4][4];
#pragma unroll
    for (int mi = 0; mi < 2; mi++)
#pragma unroll
        for (int ni = 0; ni < 4; ni++)
#pragma unroll
            for (int r = 0; r < 4; r++) acc[mi][ni][r] = 0.0f;

    int a_row_in_frag = ((lane & 8) ? 8 : 0) + (lane & 7);
    int a_chalf       = (lane >> 4);
    int b_row_in_frag = ((lane & 16) ? 8 : 0) + (lane & 7);
    int b_chalf       = ((lane >> 3) & 1);

    float4 wreg[4];   // W fp32 prefetch: 16 floats/thread per K-chunk

    auto issueA = [&](int k0, int buf) {
        uint32_t st = sbase + buf * STAGE;
#pragma unroll
        for (int i = 0; i < 2; i++) {
            int lid = tid + i * 512;          // 0..1023
            int r   = lid >> 3;
            int c   = lid & 7;
            int sw  = ((c ^ (r & 7)) << 4) + r * 128;
            long ga = (long)(bm + r) * K_DIM + k0 + c * 8;
            cp_async16(st + SM_AH + sw, g_yh + ga);
            cp_async16(st + SM_AL + sw, g_yl + ga);
        }
        asm volatile("cp.async.commit_group;\n" ::: "memory");
    };

    auto issueW = [&](int k0) {
#pragma unroll
        for (int i = 0; i < 2; i++) {
            int p    = tid + i * 512;         // 0..1023 (row, 8-col group)
            int row  = p >> 3;
            int c8   = p & 7;
            int grow = (row < 64) ? (bn64 + row) : (960 + bn64 + row);
            const float* src = W + (long)grow * K_DIM + k0 + c8 * 8;
            wreg[2 * i]     = *(const float4*)src;
            wreg[2 * i + 1] = *(const float4*)(src + 4);
        }
    };

    auto stsW = [&](int buf) {
        char* st = smem + buf * STAGE;
#pragma unroll
        for (int i = 0; i < 2; i++) {
            int p   = tid + i * 512;
            int row = p >> 3;
            int c8  = p & 7;
            int sw  = ((c8 ^ (row & 7)) << 4) + row * 128;
            const float* v = (const float*)&wreg[2 * i];
            __nv_bfloat16 h[8], l[8];
#pragma unroll
            for (int j = 0; j < 8; j++) {
                h[j] = __float2bfloat16_rn(v[j]);
                l[j] = __float2bfloat16_rn(v[j] - __bfloat162float(h[j]));
            }
            *(uint4*)(st + SM_BH + sw) = *(uint4*)h;
            *(uint4*)(st + SM_BL + sw) = *(uint4*)l;
        }
    };

    auto compute = [&](int buf) {
        uint32_t st = sbase + buf * STAGE;
#pragma unroll
        for (int term = 0; term < 3; term++) {
            uint32_t abase = st + (term == 1 ? SM_AL : SM_AH);
            uint32_t bbase = st + (term == 2 ? SM_BL : SM_BH);
#pragma unroll
            for (int ks = 0; ks < 4; ks++) {
                uint32_t af[2][4];
#pragma unroll
                for (int mi = 0; mi < 2; mi++) {
                    int arow = wm + mi * 16 + a_row_in_frag;
                    int ac   = ks * 2 + a_chalf;
                    ldsm_x4(af[mi][0], af[mi][1], af[mi][2], af[mi][3],
                            abase + arow * 128 + ((ac ^ (arow & 7)) << 4));
                }
                uint32_t bfr[2][4];
#pragma unroll
                for (int pi = 0; pi < 2; pi++) {
                    int brow = wn + pi * 16 + b_row_in_frag;
                    int bc   = ks * 2 + b_chalf;
                    ldsm_x4(bfr[pi][0], bfr[pi][1], bfr[pi][2], bfr[pi][3],
                            bbase + brow * 128 + ((bc ^ (brow & 7)) << 4));
                }
#pragma unroll
                for (int mi = 0; mi < 2; mi++)
#pragma unroll
                    for (int ni = 0; ni < 4; ni++) {
                        int pi = ni >> 1, sel = (ni & 1) * 2;
                        mma_16816(acc[mi][ni], af[mi],
                                  bfr[pi][sel + 0], bfr[pi][sel + 1]);
                    }
            }
        }
    };

    // ---- pipelined mainloop ----
    issueW(0);
    issueA(0, 0);
    stsW(0);

    int buf = 0;
#pragma unroll 1
    for (int c = 0; c < 16; c++) {
        if (c < 15) {
            int k0n = (c + 1) * GBK;
            issueW(k0n);
            issueA(k0n, buf ^ 1);
            asm volatile("cp.async.wait_group 1;\n" ::: "memory");
        } else {
            asm volatile("cp.async.wait_group 0;\n" ::: "memory");
        }
        __syncthreads();
        compute(buf);
        if (c < 15) stsW(buf ^ 1);
        __syncthreads();
        buf ^= 1;
    }

    // ---- epilogue: stage z in smem, apply bias + GLU, write y_out ----
    float* zs = (float*)smem;
#pragma unroll
    for (int mi = 0; mi < 2; mi++) {
#pragma unroll
        for (int ni = 0; ni < 4; ni++) {
            int r0  = wm + mi * 16 + (lane >> 2);
            int col = wn + ni * 8 + (lane & 3) * 2;
            zs[r0 * ZS_STRIDE + col]           = acc[mi][ni][0];
            zs[r0 * ZS_STRIDE + col + 1]       = acc[mi][ni][1];
            zs[(r0 + 8) * ZS_STRIDE + col]     = acc[mi][ni][2];
            zs[(r0 + 8) * ZS_STRIDE + col + 1] = acc[mi][ni][3];
        }
    }
    __syncthreads();

#pragma unroll
    for (int i = 0; i < 4; i++) {
        int idx = tid + i * 512;          // 0..2047: one float4 group each
        int m   = idx >> 4;               // 0..127
        int j4  = (idx & 15) * 4;         // 0..60
        float4 z1 = *(float4*)(zs + m * ZS_STRIDE + j4);
        float4 z2 = *(float4*)(zs + m * ZS_STRIDE + 64 + j4);
        float4 b1 = *(const float4*)(bias + bn64 + j4);
        float4 b2 = *(const float4*)(bias + 1024 + bn64 + j4);
        float4 o;
        o.x = (z1.x + b1.x) / (1.0f + expf(-(z2.x + b2.x)));
        o.y = (z1.y + b1.y) / (1.0f + expf(-(z2.y + b2.y)));
        o.z = (z1.z + b1.z) / (1.0f + expf(-(z2.z + b2.z)));
        o.w = (z1.w + b1.w) / (1.0f + expf(-(z2.w + b2.w)));
        *(float4*)(y_out + (long)(bm + m) * H_SZ + bn64 + j4) = o;
    }
}

// ---------------------------------------------------------------------------
extern "C" void kernel_launch(void* const* d_in, const int* in_sizes, int n_in,
                              void* d_out, int out_size)
{
    const float* u        = (const float*)d_in[0];
    const float* state_re = (const float*)d_in[1];
    const float* state_im = (const float*)d_in[2];
    const float* dA_re    = (const float*)d_in[3];
    const float* dA_im    = (const float*)d_in[4];
    const float* dB_re    = (const float*)d_in[5];
    const float* dB_im    = (const float*)d_in[6];
    const float* C_re     = (const float*)d_in[7];
    const float* C_im     = (const float*)d_in[8];
    const float* D        = (const float*)d_in[9];
    const float* W        = (const float*)d_in[10];
    const float* bias     = (const float*)d_in[11];

    float* out   = (float*)d_out;
    float* y_out = out;                                   // [B, H]
    float* ns_re = out + (long)B_SZ * H_SZ;               // [B, H, N]
    float* ns_im = ns_re + (long)B_SZ * H_SZ * N_SZ;      // [B, H, N]

    static bool attr_set = false;
    if (!attr_set) {
        cudaFuncSetAttribute(gemm_fused_kernel,
                             cudaFuncAttributeMaxDynamicSharedMemorySize, SM_TOTAL);
        attr_set = true;
    }

    // 1: state update + readout + gelu -> g_yh/g_yl (and ns outputs)
    s4_update_kernel<<<B_SZ * H_SZ * 8 / 256, 256>>>(
        u, state_re, state_im, dA_re, dA_im, dB_re, dB_im,
        C_re, C_im, D, ns_re, ns_im);

    // 2: fused GEMM + bias + GLU -> y_out
    {
        dim3 grid(16, 8);   // 16 paired-column tiles x 8 M tiles = 128 CTAs
        gemm_fused_kernel<<<grid, 512, SM_TOTAL>>>(W, bias, y_out);
    }
}

// round 11
// speedup vs baseline: 1.0984x; 1.0984x over previous
#include <cuda_runtime.h>
#include <cuda_bf16.h>
#include <math.h>
#include <stdint.h>

#define B_SZ 1024
#define H_SZ 1024
#define N_SZ 32
#define K_DIM 1024   // = H
#define N2_DIM 2048  // = 2H

// ---------------------------------------------------------------------------
// Scratch (device globals: no allocation allowed)
// ---------------------------------------------------------------------------
__device__ __nv_bfloat16 g_yh[B_SZ * H_SZ];       // hi(gelu(y+uD))
__device__ __nv_bfloat16 g_yl[B_SZ * H_SZ];       // lo residual
__device__ __nv_bfloat16 g_wh[N2_DIM * K_DIM];    // hi(W)
__device__ __nv_bfloat16 g_wl[N2_DIM * K_DIM];    // lo residual

// ---------------------------------------------------------------------------
// Kernel 0: split W into bf16 hi/lo (streaming, ~4us)
// ---------------------------------------------------------------------------
__global__ __launch_bounds__(256) void convert_w_kernel(const float* __restrict__ W)
{
    int i = blockIdx.x * 256 + threadIdx.x;        // 8 elems per thread
    const float4* w4 = (const float4*)W + (long)i * 2;
    float4 a = __ldcs(w4), b = __ldcs(w4 + 1);
    float v[8] = {a.x, a.y, a.z, a.w, b.x, b.y, b.z, b.w};

    __nv_bfloat16 h[8], l[8];
#pragma unroll
    for (int j = 0; j < 8; j++) {
        h[j] = __float2bfloat16_rn(v[j]);
        l[j] = __float2bfloat16_rn(v[j] - __bfloat162float(h[j]));
    }
    *(uint4*)(g_wh + (long)i * 8) = *(uint4*)h;
    *(uint4*)(g_wl + (long)i * 8) = *(uint4*)l;
}

// ---------------------------------------------------------------------------
// Kernel 1: complex diag state update + C-readout + GELU skip -> bf16 hi/lo
// 8 threads per (b,h) row, float4 per thread over N=32.  Streaming accesses.
// ---------------------------------------------------------------------------
__global__ __launch_bounds__(256) void s4_update_kernel(
    const float* __restrict__ u,
    const float* __restrict__ sre, const float* __restrict__ sim,
    const float* __restrict__ dAr, const float* __restrict__ dAi,
    const float* __restrict__ dBr, const float* __restrict__ dBi,
    const float* __restrict__ Cr,  const float* __restrict__ Ci,
    const float* __restrict__ D,
    float* __restrict__ ns_re, float* __restrict__ ns_im)
{
    int tid = blockIdx.x * 256 + threadIdx.x;
    int row = tid >> 3;
    int sub = tid & 7;
    int h   = row & (H_SZ - 1);

    long soff = (long)row * N_SZ + sub * 4;
    long poff = (long)h   * N_SZ + sub * 4;

    float4 s_re = __ldcs((const float4*)(sre + soff));
    float4 s_im = __ldcs((const float4*)(sim + soff));
    float4 ar   = *(const float4*)(dAr + poff);
    float4 ai   = *(const float4*)(dAi + poff);
    float4 br   = *(const float4*)(dBr + poff);
    float4 bi   = *(const float4*)(dBi + poff);
    float4 cr   = *(const float4*)(Cr  + poff);
    float4 ci   = *(const float4*)(Ci  + poff);
    float  uv   = u[row];

    float4 nr, ni;
    nr.x = ar.x * s_re.x - ai.x * s_im.x + br.x * uv;
    nr.y = ar.y * s_re.y - ai.y * s_im.y + br.y * uv;
    nr.z = ar.z * s_re.z - ai.z * s_im.z + br.z * uv;
    nr.w = ar.w * s_re.w - ai.w * s_im.w + br.w * uv;
    ni.x = ar.x * s_im.x + ai.x * s_re.x + bi.x * uv;
    ni.y = ar.y * s_im.y + ai.y * s_re.y + bi.y * uv;
    ni.z = ar.z * s_im.z + ai.z * s_re.z + bi.z * uv;
    ni.w = ar.w * s_im.w + ai.w * s_re.w + bi.w * uv;

    __stcs((float4*)(ns_re + soff), nr);
    __stcs((float4*)(ns_im + soff), ni);

    float acc = cr.x * nr.x - ci.x * ni.x
              + cr.y * nr.y - ci.y * ni.y
              + cr.z * nr.z - ci.z * ni.z
              + cr.w * nr.w - ci.w * ni.w;

    acc += __shfl_xor_sync(0xffffffffu, acc, 4);
    acc += __shfl_xor_sync(0xffffffffu, acc, 2);
    acc += __shfl_xor_sync(0xffffffffu, acc, 1);

    if (sub == 0) {
        float y = 2.0f * acc + uv * D[h];
        float g = 0.5f * y * (1.0f + erff(y * 0.70710678118654752f));
        __nv_bfloat16 hi = __float2bfloat16_rn(g);
        g_yh[row] = hi;
        g_yl[row] = __float2bfloat16_rn(g - __bfloat162float(hi));
    }
}

// ---------------------------------------------------------------------------
// Kernel 2 (fused): split-bf16 tensor GEMM + bias + GLU -> y_out
// 256 threads / 8 warps (2M x 4N grid, warp tile 64x32).
// CTA: M-tile 128, paired N columns [bn64,+64) and [1024+bn64,+64).
// K-chunk 64, 3-stage cp.async pipeline (all 4 tiles bf16), ONE barrier per
// chunk.  Fragments loaded once per ks and reused across the 3 split terms.
// ---------------------------------------------------------------------------
__device__ __forceinline__ void ldsm_x4(uint32_t& r0, uint32_t& r1,
                                        uint32_t& r2, uint32_t& r3, uint32_t addr)
{
    asm volatile("ldmatrix.sync.aligned.m8n8.x4.shared.b16 {%0,%1,%2,%3}, [%4];\n"
                 : "=r"(r0), "=r"(r1), "=r"(r2), "=r"(r3) : "r"(addr));
}

__device__ __forceinline__ void mma_16816(float* c, const uint32_t* a,
                                          uint32_t b0, uint32_t b1)
{
    asm volatile(
        "mma.sync.aligned.m16n8k16.row.col.f32.bf16.bf16.f32 "
        "{%0,%1,%2,%3}, {%4,%5,%6,%7}, {%8,%9}, {%0,%1,%2,%3};\n"
        : "+f"(c[0]), "+f"(c[1]), "+f"(c[2]), "+f"(c[3])
        : "r"(a[0]), "r"(a[1]), "r"(a[2]), "r"(a[3]), "r"(b0), "r"(b1));
}

__device__ __forceinline__ void cp_async16(uint32_t dst, const void* src)
{
    asm volatile("cp.async.cg.shared.global [%0], [%1], 16;\n"
                 :: "r"(dst), "l"(src));
}

#define GBK    64
#define SM_AH  0
#define SM_AL  16384
#define SM_BH  32768
#define SM_BL  49152
#define STAGE  65536
#define NSTAGE 3
#define SM_TOTAL (NSTAGE * STAGE)     // 192 KB
#define ZS_STRIDE 132                 // fp32 z staging stride

__global__ __launch_bounds__(256, 1) void gemm_fused_kernel(
    const float* __restrict__ bias,
    float* __restrict__ y_out)
{
    extern __shared__ char smem[];
    uint32_t sbase = (uint32_t)__cvta_generic_to_shared(smem);

    int tid  = threadIdx.x;
    int lane = tid & 31;
    int wid  = tid >> 5;
    int wm   = (wid & 1) * 64;     // warp M offset
    int wn   = (wid >> 1) * 32;    // warp N offset
    int bm   = blockIdx.y * 128;
    int bn64 = blockIdx.x * 64;    // first-half column base

    float acc[4][4][4];
#pragma unroll
    for (int mi = 0; mi < 4; mi++)
#pragma unroll
        for (int ni = 0; ni < 4; ni++)
#pragma unroll
            for (int r = 0; r < 4; r++) acc[mi][ni][r] = 0.0f;

    int a_row_in_frag = ((lane & 8) ? 8 : 0) + (lane & 7);
    int a_chalf       = (lane >> 4);
    int b_row_in_frag = ((lane & 16) ? 8 : 0) + (lane & 7);
    int b_chalf       = ((lane >> 3) & 1);

    auto issue = [&](int k0, int slot) {
        uint32_t st = sbase + slot * STAGE;
#pragma unroll
        for (int i = 0; i < 4; i++) {
            int lid = tid + i * 256;          // 0..1023
            int r   = lid >> 3;
            int c   = lid & 7;
            int sw  = ((c ^ (r & 7)) << 4) + r * 128;
            long ga = (long)(bm + r) * K_DIM + k0 + c * 8;
            int grow = (r < 64) ? (bn64 + r) : (960 + bn64 + r);
            long gb = (long)grow * K_DIM + k0 + c * 8;
            cp_async16(st + SM_AH + sw, g_yh + ga);
            cp_async16(st + SM_AL + sw, g_yl + ga);
            cp_async16(st + SM_BH + sw, g_wh + gb);
            cp_async16(st + SM_BL + sw, g_wl + gb);
        }
        asm volatile("cp.async.commit_group;\n" ::: "memory");
    };

    auto compute = [&](int slot) {
        uint32_t st = sbase + slot * STAGE;
#pragma unroll
        for (int ks = 0; ks < 4; ks++) {
            // ---- load all fragments once ----
            uint32_t ah[4][4], al[4][4];
#pragma unroll
            for (int mi = 0; mi < 4; mi++) {
                int arow = wm + mi * 16 + a_row_in_frag;
                int ac   = ks * 2 + a_chalf;
                uint32_t off = arow * 128 + ((ac ^ (arow & 7)) << 4);
                ldsm_x4(ah[mi][0], ah[mi][1], ah[mi][2], ah[mi][3],
                        st + SM_AH + off);
                ldsm_x4(al[mi][0], al[mi][1], al[mi][2], al[mi][3],
                        st + SM_AL + off);
            }
            uint32_t bh[2][4], bl[2][4];
#pragma unroll
            for (int pi = 0; pi < 2; pi++) {
                int brow = wn + pi * 16 + b_row_in_frag;
                int bc   = ks * 2 + b_chalf;
                uint32_t off = brow * 128 + ((bc ^ (brow & 7)) << 4);
                ldsm_x4(bh[pi][0], bh[pi][1], bh[pi][2], bh[pi][3],
                        st + SM_BH + off);
                ldsm_x4(bl[pi][0], bl[pi][1], bl[pi][2], bl[pi][3],
                        st + SM_BL + off);
            }
            // ---- 3 split terms from registers ----
#pragma unroll
            for (int mi = 0; mi < 4; mi++)
#pragma unroll
                for (int ni = 0; ni < 4; ni++) {
                    int pi = ni >> 1, sel = (ni & 1) * 2;
                    mma_16816(acc[mi][ni], ah[mi], bh[pi][sel], bh[pi][sel + 1]);
                    mma_16816(acc[mi][ni], ah[mi], bl[pi][sel], bl[pi][sel + 1]);
                    mma_16816(acc[mi][ni], al[mi], bh[pi][sel], bh[pi][sel + 1]);
                }
        }
    };

    // ---- multistage mainloop: one barrier per chunk ----
    issue(0, 0);
    issue(GBK, 1);

#pragma unroll 1
    for (int c = 0; c < 16; c++) {
        if (c < 15)
            asm volatile("cp.async.wait_group 1;\n" ::: "memory");
        else
            asm volatile("cp.async.wait_group 0;\n" ::: "memory");
        __syncthreads();
        if (c + 2 < 16) issue((c + 2) * GBK, (c + 2) % NSTAGE);
        compute(c % NSTAGE);
    }

    // ---- epilogue: stage z in smem, apply bias + GLU, write y_out ----
    __syncthreads();
    float* zs = (float*)smem;
#pragma unroll
    for (int mi = 0; mi < 4; mi++) {
#pragma unroll
        for (int ni = 0; ni < 4; ni++) {
            int r0  = wm + mi * 16 + (lane >> 2);
            int col = wn + ni * 8 + (lane & 3) * 2;
            zs[r0 * ZS_STRIDE + col]           = acc[mi][ni][0];
            zs[r0 * ZS_STRIDE + col + 1]       = acc[mi][ni][1];
            zs[(r0 + 8) * ZS_STRIDE + col]     = acc[mi][ni][2];
            zs[(r0 + 8) * ZS_STRIDE + col + 1] = acc[mi][ni][3];
        }
    }
    __syncthreads();

#pragma unroll
    for (int i = 0; i < 8; i++) {
        int idx = tid + i * 256;          // 0..2047
        int m   = idx >> 4;               // 0..127
        int j4  = (idx & 15) * 4;         // 0..60
        float4 z1 = *(float4*)(zs + m * ZS_STRIDE + j4);
        float4 z2 = *(float4*)(zs + m * ZS_STRIDE + 64 + j4);
        float4 b1 = *(const float4*)(bias + bn64 + j4);
        float4 b2 = *(const float4*)(bias + 1024 + bn64 + j4);
        float4 o;
        o.x = (z1.x + b1.x) / (1.0f + expf(-(z2.x + b2.x)));
        o.y = (z1.y + b1.y) / (1.0f + expf(-(z2.y + b2.y)));
        o.z = (z1.z + b1.z) / (1.0f + expf(-(z2.z + b2.z)));
        o.w = (z1.w + b1.w) / (1.0f + expf(-(z2.w + b2.w)));
        *(float4*)(y_out + (long)(bm + m) * H_SZ + bn64 + j4) = o;
    }
}

// ---------------------------------------------------------------------------
extern "C" void kernel_launch(void* const* d_in, const int* in_sizes, int n_in,
                              void* d_out, int out_size)
{
    const float* u        = (const float*)d_in[0];
    const float* state_re = (const float*)d_in[1];
    const float* state_im = (const float*)d_in[2];
    const float* dA_re    = (const float*)d_in[3];
    const float* dA_im    = (const float*)d_in[4];
    const float* dB_re    = (const float*)d_in[5];
    const float* dB_im    = (const float*)d_in[6];
    const float* C_re     = (const float*)d_in[7];
    const float* C_im     = (const float*)d_in[8];
    const float* D        = (const float*)d_in[9];
    const float* W        = (const float*)d_in[10];
    const float* bias     = (const float*)d_in[11];

    float* out   = (float*)d_out;
    float* y_out = out;                                   // [B, H]
    float* ns_re = out + (long)B_SZ * H_SZ;               // [B, H, N]
    float* ns_im = ns_re + (long)B_SZ * H_SZ * N_SZ;      // [B, H, N]

    static bool attr_set = false;
    if (!attr_set) {
        cudaFuncSetAttribute(gemm_fused_kernel,
                             cudaFuncAttributeMaxDynamicSharedMemorySize, SM_TOTAL);
        attr_set = true;
    }

    // 0: W -> bf16 hi/lo
    convert_w_kernel<<<(N2_DIM * K_DIM / 8) / 256, 256>>>(W);

    // 1: state update + readout + gelu -> g_yh/g_yl (and ns outputs)
    s4_update_kernel<<<B_SZ * H_SZ * 8 / 256, 256>>>(
        u, state_re, state_im, dA_re, dA_im, dB_re, dB_im,
        C_re, C_im, D, ns_re, ns_im);

    // 2: fused GEMM + bias + GLU -> y_out
    {
        dim3 grid(16, 8);   // 16 paired-column tiles x 8 M tiles = 128 CTAs
        gemm_fused_kernel<<<grid, 256, SM_TOTAL>>>(bias, y_out);
    }
}